// round 2
// baseline (speedup 1.0000x reference)
#include <cuda_runtime.h>
#include <math_constants.h>

#define Bc 8
#define Lc 4096
#define Hc 8
#define Dc 64
#define Sc 45
#define Uc 45
#define BHc (Bc*Hc)
#define NSPLIT 4
#define KSPLIT (Lc/NSPLIT)
#define TK 64
#define NCH 32
#define CHL (Lc/NCH)

// ---- scratch (__device__ globals; no allocation allowed) ----
__device__ int   g_idx[Lc*Sc];
__device__ int   g_mode64;
__device__ float g_M[BHc*Lc];
__device__ int   g_top[BHc*Uc];
__device__ float g_pm[BHc*Uc*NSPLIT];
__device__ float g_pl[BHc*Uc*NSPLIT];
__device__ float g_pacc[BHc*Uc*NSPLIT*Dc];
__device__ float g_vagg[BHc*Uc*Dc];
__device__ float g_ps[Bc*NCH*Hc*Dc];

// ============================================================
// K0a: detect whether index buffer is int64 or int32.
// View as uint32[count] (always in-bounds). If int64 (LE), odd
// positions are high words == 0; if int32, they are random indices.
// ============================================================
__global__ void k0_detect(const unsigned int* __restrict__ p)
{
    __shared__ unsigned int red[256];
    unsigned int acc = 0;
    for (int j = 1 + 2*threadIdx.x; j < Lc*Sc; j += 512) acc |= p[j];
    red[threadIdx.x] = acc;
    __syncthreads();
    for (int o = 128; o > 0; o >>= 1) {
        if (threadIdx.x < o) red[threadIdx.x] |= red[threadIdx.x + o];
        __syncthreads();
    }
    if (threadIdx.x == 0) g_mode64 = (red[0] == 0u) ? 1 : 0;
}

// K0b: normalize indices into int32 scratch
__global__ void k0_convert(const void* __restrict__ raw)
{
    int i = blockIdx.x * 256 + threadIdx.x;
    if (i >= Lc*Sc) return;
    if (g_mode64) g_idx[i] = (int)((const long long*)raw)[i];
    else          g_idx[i] = ((const int*)raw)[i];
}

// ============================================================
// K1: M[b,h,q] = max_s(Q[q]·K[idx[q,s]]) - sum_s(...)/L
// 8-lane groups, 256B K row per gather (2x float4 per lane), s unrolled x3
// ============================================================
__global__ void __launch_bounds__(256) k1_sample_scores(
    const float* __restrict__ Q, const float* __restrict__ K)
{
    int bh = blockIdx.y;
    int b = bh >> 3, h = bh & 7;
    int g = threadIdx.x >> 3;   // 32 groups of 8
    int t = threadIdx.x & 7;
    const float4* Q4 = (const float4*)Q;
    const float4* K4 = (const float4*)K;

    #pragma unroll
    for (int i = 0; i < 4; i++) {
        int q = blockIdx.x * 128 + g * 4 + i;
        int qrb = (((b * Lc + q) * Hc + h) * Dc) >> 2;
        float4 qa = Q4[qrb + t];
        float4 qb = Q4[qrb + 8 + t];
        const int* ip = g_idx + q * Sc;
        float maxv = -CUDART_INF_F, sumv = 0.f;
        for (int s = 0; s < Sc; s += 3) {
            int k0 = ip[s], k1 = ip[s+1], k2 = ip[s+2];
            int r0 = (((b * Lc + k0) * Hc + h) * Dc) >> 2;
            int r1 = (((b * Lc + k1) * Hc + h) * Dc) >> 2;
            int r2 = (((b * Lc + k2) * Hc + h) * Dc) >> 2;
            float4 a0 = K4[r0 + t], c0 = K4[r0 + 8 + t];
            float4 a1 = K4[r1 + t], c1 = K4[r1 + 8 + t];
            float4 a2 = K4[r2 + t], c2 = K4[r2 + 8 + t];
            float p0 = qa.x*a0.x + qa.y*a0.y + qa.z*a0.z + qa.w*a0.w
                     + qb.x*c0.x + qb.y*c0.y + qb.z*c0.z + qb.w*c0.w;
            float p1 = qa.x*a1.x + qa.y*a1.y + qa.z*a1.z + qa.w*a1.w
                     + qb.x*c1.x + qb.y*c1.y + qb.z*c1.z + qb.w*c1.w;
            float p2 = qa.x*a2.x + qa.y*a2.y + qa.z*a2.z + qa.w*a2.w
                     + qb.x*c2.x + qb.y*c2.y + qb.z*c2.z + qb.w*c2.w;
            p0 += __shfl_down_sync(0xffffffffu, p0, 4, 8);
            p0 += __shfl_down_sync(0xffffffffu, p0, 2, 8);
            p0 += __shfl_down_sync(0xffffffffu, p0, 1, 8);
            p1 += __shfl_down_sync(0xffffffffu, p1, 4, 8);
            p1 += __shfl_down_sync(0xffffffffu, p1, 2, 8);
            p1 += __shfl_down_sync(0xffffffffu, p1, 1, 8);
            p2 += __shfl_down_sync(0xffffffffu, p2, 4, 8);
            p2 += __shfl_down_sync(0xffffffffu, p2, 2, 8);
            p2 += __shfl_down_sync(0xffffffffu, p2, 1, 8);
            // values valid on t==0 only; other lanes carry junk (unused)
            maxv = fmaxf(maxv, fmaxf(p0, fmaxf(p1, p2)));
            sumv += p0 + p1 + p2;
        }
        if (t == 0) g_M[bh * Lc + q] = maxv - sumv * (1.0f / (float)Lc);
    }
}

// ============================================================
// K2: top-45 per (b,h) via iterative argmax over SMEM copy
// ============================================================
__global__ void __launch_bounds__(256) k2_topk()
{
    __shared__ float sv[Lc];
    __shared__ float rv[256];
    __shared__ int   ri[256];
    int bh = blockIdx.x, tid = threadIdx.x;
    for (int i = tid; i < Lc; i += 256) sv[i] = g_M[bh*Lc + i];
    __syncthreads();
    for (int r = 0; r < Uc; r++) {
        float best = -CUDART_INF_F; int bi = 0;
        for (int i = tid; i < Lc; i += 256) {
            float v = sv[i];
            if (v > best) { best = v; bi = i; }
        }
        rv[tid] = best; ri[tid] = bi;
        __syncthreads();
        for (int o = 128; o > 0; o >>= 1) {
            if (tid < o && rv[tid+o] > rv[tid]) { rv[tid] = rv[tid+o]; ri[tid] = ri[tid+o]; }
            __syncthreads();
        }
        if (tid == 0) { g_top[bh*Uc + r] = ri[0]; sv[ri[0]] = -CUDART_INF_F; }
        __syncthreads();
    }
}

// ============================================================
// K3: flash-style attention for the 45 selected queries,
// split-KV across 4 blocks per (b,h). Online softmax partials.
// ============================================================
__global__ void __launch_bounds__(512) k3_attn(
    const float* __restrict__ Q, const float* __restrict__ K,
    const float* __restrict__ V)
{
    __shared__ float Qs[Uc][Dc];
    __shared__ int   qpos_s[Uc];
    __shared__ float Kt[Dc][TK+1];   // d-major (transposed)
    __shared__ float Vt[TK][Dc];
    int split = blockIdx.x, bh = blockIdx.y;
    int b = bh >> 3, h = bh & 7;
    int tid = threadIdx.x, lane = tid & 31, w = tid >> 5;

    if (tid < Uc) qpos_s[tid] = g_top[bh*Uc + tid];
    __syncthreads();
    for (int i = tid; i < Uc*Dc; i += 512) {
        int u = i >> 6, d = i & 63;
        int qp = qpos_s[u];
        Qs[u][d] = Q[(((b*Lc + qp)*Hc + h) << 6) + d] * 0.125f; // pre-scaled
    }
    __syncthreads();

    int maxqp = 0;
    for (int u = 0; u < Uc; u++) maxqp = max(maxqp, qpos_s[u]);
    int kb0 = split * KSPLIT;
    int ntiles = 0;
    if (maxqp >= kb0) {
        int nn = (maxqp - kb0) / TK + 1;
        ntiles = nn < (KSPLIT/TK) ? nn : (KSPLIT/TK);
    }

    float m[3], lsum[3], acc0[3], acc1[3];
    #pragma unroll
    for (int j = 0; j < 3; j++) { m[j] = -CUDART_INF_F; lsum[j]=0.f; acc0[j]=0.f; acc1[j]=0.f; }

    for (int tile = 0; tile < ntiles; tile++) {
        int kb = kb0 + tile * TK;
        for (int i = tid; i < TK*Dc; i += 512) {
            int k = i >> 6, d = i & 63;
            int gbase = (((b*Lc + kb + k)*Hc + h) << 6) + d;
            Kt[d][k] = K[gbase];
            Vt[k][d] = V[gbase];
        }
        __syncthreads();
        #pragma unroll
        for (int j = 0; j < 3; j++) {
            int u = w*3 + j;
            if (u >= Uc) continue;
            int qp = qpos_s[u];
            if (qp < kb) continue;            // fully masked tile for this query
            int nk = min(TK, qp - kb + 1);
            float s0 = 0.f, s1 = 0.f;
            #pragma unroll 8
            for (int d = 0; d < Dc; d++) {
                float qd = Qs[u][d];
                s0 += qd * Kt[d][lane];
                s1 += qd * Kt[d][lane+32];
            }
            if (lane >= nk)      s0 = -CUDART_INF_F;
            if (lane + 32 >= nk) s1 = -CUDART_INF_F;
            float tm = fmaxf(s0, s1);
            #pragma unroll
            for (int o = 16; o > 0; o >>= 1) tm = fmaxf(tm, __shfl_xor_sync(0xffffffffu, tm, o));
            float newm = fmaxf(m[j], tm);
            float p0 = __expf(s0 - newm);
            float p1 = __expf(s1 - newm);
            float ps = p0 + p1;
            #pragma unroll
            for (int o = 16; o > 0; o >>= 1) ps += __shfl_xor_sync(0xffffffffu, ps, o);
            float c = __expf(m[j] - newm);
            lsum[j] = lsum[j]*c + ps;
            m[j] = newm;
            acc0[j] *= c; acc1[j] *= c;
            for (int k = 0; k < nk; k++) {
                float pk = __shfl_sync(0xffffffffu, (k < 32) ? p0 : p1, k & 31);
                acc0[j] += pk * Vt[k][lane];
                acc1[j] += pk * Vt[k][lane+32];
            }
        }
        __syncthreads();
    }

    #pragma unroll
    for (int j = 0; j < 3; j++) {
        int u = w*3 + j;
        if (u >= Uc) continue;
        int base = (bh*Uc + u)*NSPLIT + split;
        if (qpos_s[u] < kb0) {
            if (lane == 0) { g_pm[base] = -CUDART_INF_F; g_pl[base] = 0.f; }
            g_pacc[base*Dc + lane] = 0.f;
            g_pacc[base*Dc + lane + 32] = 0.f;
        } else {
            if (lane == 0) { g_pm[base] = m[j]; g_pl[base] = lsum[j]; }
            g_pacc[base*Dc + lane] = acc0[j];
            g_pacc[base*Dc + lane + 32] = acc1[j];
        }
    }
}

// K3b: combine split-KV partials -> values_agg
__global__ void __launch_bounds__(64) k3b_combine()
{
    int u = blockIdx.x, bh = blockIdx.y, d = threadIdx.x;
    int base = (bh*Uc + u)*NSPLIT;
    float pm[NSPLIT], pl[NSPLIT];
    float M = -CUDART_INF_F;
    #pragma unroll
    for (int s = 0; s < NSPLIT; s++) {
        pm[s] = g_pm[base+s]; pl[s] = g_pl[base+s];
        M = fmaxf(M, pm[s]);
    }
    float Ls = 0.f, r = 0.f;
    #pragma unroll
    for (int s = 0; s < NSPLIT; s++) {
        float e = __expf(pm[s] - M);     // -inf -> 0
        Ls += pl[s] * e;
        r  += g_pacc[(base+s)*Dc + d] * e;
    }
    g_vagg[(bh*Uc + u)*Dc + d] = r / Ls;
}

// ============================================================
// K4: chunked cumsum of V over L (3 passes for occupancy)
// ============================================================
__global__ void __launch_bounds__(512) k4a_partials(const float* __restrict__ V)
{
    int b = blockIdx.x, ch = blockIdx.y, tid = threadIdx.x; // tid = h*64+d
    float s = 0.f;
    int base = (b*Lc + ch*CHL) * (Hc*Dc) + tid;
    for (int l = 0; l < CHL; l++) s += V[base + l*(Hc*Dc)];
    g_ps[(b*NCH + ch)*(Hc*Dc) + tid] = s;
}

__global__ void __launch_bounds__(512) k4b_prefix()
{
    int b = blockIdx.x, tid = threadIdx.x;
    float run = 0.f;
    for (int ch = 0; ch < NCH; ch++) {
        int o = (b*NCH + ch)*(Hc*Dc) + tid;
        float t = g_ps[o]; g_ps[o] = run; run += t;
    }
}

__global__ void __launch_bounds__(512) k4c_cumsum(const float* __restrict__ V,
                                                  float* __restrict__ out)
{
    int b = blockIdx.x, ch = blockIdx.y, tid = threadIdx.x;
    float acc = g_ps[(b*NCH + ch)*(Hc*Dc) + tid];
    int base = (b*Lc + ch*CHL) * (Hc*Dc) + tid;
    for (int l = 0; l < CHL; l++) {
        acc += V[base + l*(Hc*Dc)];
        out[base + l*(Hc*Dc)] = acc;
    }
}

// K5: scatter values_agg over cumsum at selected rows
__global__ void __launch_bounds__(64) k5_scatter(float* __restrict__ out)
{
    int u = blockIdx.x, bh = blockIdx.y, d = threadIdx.x;
    int b = bh >> 3, h = bh & 7;
    int qp = g_top[bh*Uc + u];
    out[(((b*Lc + qp)*Hc + h) << 6) + d] = g_vagg[(bh*Uc + u)*Dc + d];
}

// ============================================================
extern "C" void kernel_launch(void* const* d_in, const int* in_sizes, int n_in,
                              void* d_out, int out_size)
{
    const float* Q = (const float*)d_in[0];
    const float* K = (const float*)d_in[1];
    const float* V = (const float*)d_in[2];
    const void*  IDXRAW = d_in[3];
    float* out = (float*)d_out;

    k0_detect<<<1, 256>>>((const unsigned int*)IDXRAW);
    k0_convert<<<(Lc*Sc + 255)/256, 256>>>(IDXRAW);
    k1_sample_scores<<<dim3(Lc/128, BHc), 256>>>(Q, K);
    k2_topk<<<BHc, 256>>>();
    k3_attn<<<dim3(NSPLIT, BHc), 512>>>(Q, K, V);
    k3b_combine<<<dim3(Uc, BHc), Dc>>>();
    k4a_partials<<<dim3(Bc, NCH), Hc*Dc>>>(V);
    k4b_prefix<<<Bc, Hc*Dc>>>();
    k4c_cumsum<<<dim3(Bc, NCH), Hc*Dc>>>(V, out);
    k5_scatter<<<dim3(Uc, BHc), Dc>>>(out);
}